// round 6
// baseline (speedup 1.0000x reference)
#include <cuda_runtime.h>
#include <math.h>

// Problem constants
#define NN 100000
#define DD 128
#define HH 8
#define CC 16
#define EE 800000
#define ETOT (EE + NN)              // 900000
#define OUT_ELEMS (NN * DD)         // 12,800,000
#define EI_ELEMS  (2 * ETOT)        //  1,800,000
#define ALPHA_ELEMS (ETOT * HH)     //  7,200,000
#define NEG_SLOPE 0.2f

#define SB 512
#define NB1 ((NN + SB - 1) / SB)    // 196 scan blocks

// GEMM tiling
#define GR 128                      // rows per block
#define GCOL 64                     // cols per block
#define XS_STRIDE 132               // padded floats per k-row of x tile
#define WS_STRIDE 68                // padded floats per k-row of W tile
#define GEMM_SMEM ((DD * XS_STRIDE + DD * WS_STRIDE) * 4)   // 102400 B

// ---------------- device scratch (static; 16B-aligned) -----------------------
__device__ __align__(16) float g_h[(size_t)NN * DD];      // 51.2 MB
__device__ __align__(16) float g_asrc[(size_t)NN * HH];   // 3.2 MB
__device__ __align__(16) float g_adst[(size_t)NN * HH];   // 3.2 MB
__device__ __align__(16) float g_wa[DD * 16];             // fused W@att (src|dst)
__device__ int g_cnt[NN];
__device__ int g_rowptr[NN + 1];
__device__ int g_fillpos[NN];
__device__ int g_bsum[256];
__device__ int g_boff[256];
__device__ int g_esrc[ETOT];
__device__ int g_eid[ETOT];
__device__ int g_stride2;   // 1 if edge buffer is int64-backed (low words, stride 2)

// ---------------- helpers ----------------------------------------------------
__device__ __forceinline__ void ffma2(unsigned long long& acc,
                                      unsigned long long x2,
                                      unsigned long long w2) {
    asm("fma.rn.f32x2 %0, %1, %2, %0;" : "+l"(acc) : "l"(x2), "l"(w2));
}
__device__ __forceinline__ float lrelu(float v) {
    return v > 0.f ? v : NEG_SLOPE * v;
}
__device__ __forceinline__ void edge_sd(const int* __restrict__ ei, int e, int st2,
                                        int& s, int& d) {
    if (e < EE) {
        if (st2) { s = ei[2 * e]; d = ei[2 * (EE + e)]; }
        else     { s = ei[e];     d = ei[EE + e]; }
    } else {
        s = d = e - EE;
    }
}

// ---------------- detect int32 vs int64 edge buffer --------------------------
__global__ void detect_kernel(const int* __restrict__ ei) {
    int nz = 0;
    #pragma unroll
    for (int i = 0; i < 64; i++) nz |= ei[2 * i + 1];
    g_stride2 = (nz == 0) ? 1 : 0;
}

// ---------------- init: zero histogram, build histogram, optional ei copy ----
__global__ void init_kernel(float* __restrict__ out, const int* __restrict__ ei,
                            int writeAll, int phase) {
    const int st2 = g_stride2;
    int i = blockIdx.x * blockDim.x + threadIdx.x;
    int stride = gridDim.x * blockDim.x;
    if (phase == 0) {
        for (int t = i; t < NN; t += stride) g_cnt[t] = 0;
    } else {
        for (int t = i; t < ETOT; t += stride) {
            int s, d;
            edge_sd(ei, t, st2, s, d);
            atomicAdd(&g_cnt[d], 1);
            if (writeAll) {
                out[(size_t)OUT_ELEMS + t]        = (float)s;
                out[(size_t)OUT_ELEMS + ETOT + t] = (float)d;
            }
        }
    }
}

// ---------------- prep: Wa[k][c] = sum_c' W[k][h*16+c'] * att[h][c'] ---------
__global__ void prep_wa_kernel(const float* __restrict__ W,
                               const float* __restrict__ as,
                               const float* __restrict__ ad) {
    int k = threadIdx.x;   // 0..127
    #pragma unroll
    for (int h = 0; h < HH; h++) {
        float s1 = 0.f, s2 = 0.f;
        #pragma unroll
        for (int c = 0; c < CC; c++) {
            float w = W[(size_t)k * DD + h * CC + c];
            s1 += w * as[h * CC + c];
            s2 += w * ad[h * CC + c];
        }
        g_wa[k * 16 + h]     = s1;
        g_wa[k * 16 + 8 + h] = s2;
    }
}

// ---------------- GEMM: h = x @ W, register-tiled 128x64 blocks --------------
// 256 threads; thread tile = 8 rows (4 f32x2 pairs) x 4 cols.
// cg = tid & 15 -> cols cg*4..cg*4+3 ; rg = tid >> 4 -> rows rg*8..rg*8+7.
__global__ void __launch_bounds__(256) gemm_kernel(const float* __restrict__ x,
                                                   const float* __restrict__ W) {
    extern __shared__ __align__(16) float sm[];
    float* xs = sm;                       // [128 k][132] (rows in cols)
    float* ws = sm + DD * XS_STRIDE;      // [128 k][68]

    const int tid  = threadIdx.x;
    const int row0 = blockIdx.x * GR;
    const int col0 = blockIdx.y * GCOL;

    // Load x tile transposed: xs[k][r] = x[row0+r][k]
    // i over (r, k4): r = i>>5, k4 = i&31 (warp reads 512B contiguous per row)
    #pragma unroll
    for (int it = 0; it < 16; it++) {
        int i = tid + 256 * it;           // 0..4095
        int r = i >> 5, k4 = (i & 31) * 4;
        int row = row0 + r;
        float4 v = (row < NN) ? *(const float4*)(x + (size_t)row * DD + k4)
                              : make_float4(0.f, 0.f, 0.f, 0.f);
        xs[(k4 + 0) * XS_STRIDE + r] = v.x;
        xs[(k4 + 1) * XS_STRIDE + r] = v.y;
        xs[(k4 + 2) * XS_STRIDE + r] = v.z;
        xs[(k4 + 3) * XS_STRIDE + r] = v.w;
    }
    // Load W tile: ws[k][c] = W[k][col0+c]
    #pragma unroll
    for (int it = 0; it < 8; it++) {
        int i = tid + 256 * it;           // 0..2047
        int k = i >> 4, c4 = (i & 15) * 4;
        float4 v = *(const float4*)(W + (size_t)k * DD + col0 + c4);
        *(float4*)(ws + k * WS_STRIDE + c4) = v;
    }
    __syncthreads();

    const int cg = tid & 15;
    const int rg = tid >> 4;
    const float* xrow = xs + rg * 8;
    const float* wrow = ws + cg * 4;

    unsigned long long acc[4][4];
    #pragma unroll
    for (int p = 0; p < 4; p++)
        #pragma unroll
        for (int c = 0; c < 4; c++) acc[p][c] = 0ull;

    #pragma unroll 4
    for (int k = 0; k < DD; k++) {
        ulonglong2 xa = *(const ulonglong2*)(xrow + k * XS_STRIDE);
        ulonglong2 xb = *(const ulonglong2*)(xrow + k * XS_STRIDE + 4);
        float4 wv = *(const float4*)(wrow + k * WS_STRIDE);
        unsigned long long w2[4];
        asm("mov.b64 %0, {%1,%1};" : "=l"(w2[0]) : "f"(wv.x));
        asm("mov.b64 %0, {%1,%1};" : "=l"(w2[1]) : "f"(wv.y));
        asm("mov.b64 %0, {%1,%1};" : "=l"(w2[2]) : "f"(wv.z));
        asm("mov.b64 %0, {%1,%1};" : "=l"(w2[3]) : "f"(wv.w));
        #pragma unroll
        for (int c = 0; c < 4; c++) {
            ffma2(acc[0][c], xa.x, w2[c]);
            ffma2(acc[1][c], xa.y, w2[c]);
            ffma2(acc[2][c], xb.x, w2[c]);
            ffma2(acc[3][c], xb.y, w2[c]);
        }
    }

    // Epilogue: acc[p][c] holds rows (rg*8+2p, rg*8+2p+1), col col0+cg*4+c
    #pragma unroll
    for (int p = 0; p < 4; p++) {
        float lo[4], hi[4];
        #pragma unroll
        for (int c = 0; c < 4; c++)
            asm("mov.b64 {%0,%1}, %2;" : "=f"(lo[c]), "=f"(hi[c]) : "l"(acc[p][c]));
        int r0 = row0 + rg * 8 + 2 * p;
        if (r0 < NN)
            *(float4*)(g_h + (size_t)r0 * DD + col0 + cg * 4) =
                make_float4(lo[0], lo[1], lo[2], lo[3]);
        if (r0 + 1 < NN)
            *(float4*)(g_h + (size_t)(r0 + 1) * DD + col0 + cg * 4) =
                make_float4(hi[0], hi[1], hi[2], hi[3]);
    }
}

// ---------------- attention dots: a = x @ Wa (skinny GEMM) -------------------
__global__ void __launch_bounds__(128) attn2_kernel(const float* __restrict__ x) {
    __shared__ __align__(16) float xs[DD * 36];
    __shared__ __align__(16) float wa_s[DD * 16];
    __shared__ float ps[4 * 32 * 17];
    const int j = threadIdx.x;
    const int row0 = blockIdx.x * 32;

    #pragma unroll 8
    for (int r = 0; r < 32; r++) {
        int row = row0 + r;
        float v = (row < NN) ? x[(size_t)row * DD + j] : 0.f;
        xs[j * 36 + r] = v;
    }
    #pragma unroll
    for (int q = 0; q < 16; q++) wa_s[q * 128 + j] = g_wa[q * 128 + j];
    __syncthreads();

    const int lane = j & 31;
    const int w    = j >> 5;
    float s[16];
    #pragma unroll
    for (int c = 0; c < 16; c++) s[c] = 0.f;
    #pragma unroll 4
    for (int kk = 0; kk < 32; kk++) {
        int k = w * 32 + kk;
        float xv = xs[k * 36 + lane];
        const float4* wp = (const float4*)(&wa_s[k * 16]);
        #pragma unroll
        for (int q = 0; q < 4; q++) {
            float4 wv = wp[q];
            s[4 * q + 0] += xv * wv.x;
            s[4 * q + 1] += xv * wv.y;
            s[4 * q + 2] += xv * wv.z;
            s[4 * q + 3] += xv * wv.w;
        }
    }
    #pragma unroll
    for (int c = 0; c < 16; c++) ps[w * 544 + lane * 17 + c] = s[c];
    __syncthreads();

    #pragma unroll
    for (int q = 0; q < 4; q++) {
        int o = j * 4 + q;
        int r = o >> 4, c = o & 15;
        float v = ps[0 * 544 + r * 17 + c] + ps[1 * 544 + r * 17 + c]
                + ps[2 * 544 + r * 17 + c] + ps[3 * 544 + r * 17 + c];
        int row = row0 + r;
        if (row < NN) {
            if (c < 8) g_asrc[(size_t)row * 8 + c] = v;
            else       g_adst[(size_t)row * 8 + (c - 8)] = v;
        }
    }
}

// ---------------- CSR build --------------------------------------------------
__global__ void scan1_kernel() {
    __shared__ int sm[SB];
    int tid = threadIdx.x;
    int gid = blockIdx.x * SB + tid;
    int v = (gid < NN) ? g_cnt[gid] : 0;
    sm[tid] = v;
    __syncthreads();
    for (int off = 1; off < SB; off <<= 1) {
        int t = (tid >= off) ? sm[tid - off] : 0;
        __syncthreads();
        sm[tid] += t;
        __syncthreads();
    }
    if (gid < NN) g_rowptr[gid] = sm[tid] - v;
    if (tid == SB - 1) g_bsum[blockIdx.x] = sm[tid];
}

__global__ void scan2_kernel() {
    __shared__ int sm[256];
    int tid = threadIdx.x;
    int v = (tid < NB1) ? g_bsum[tid] : 0;
    sm[tid] = v;
    __syncthreads();
    for (int off = 1; off < 256; off <<= 1) {
        int t = (tid >= off) ? sm[tid - off] : 0;
        __syncthreads();
        sm[tid] += t;
        __syncthreads();
    }
    g_boff[tid] = sm[tid] - v;
}

__global__ void scan3_kernel() {
    int tid = threadIdx.x;
    int gid = blockIdx.x * SB + tid;
    if (gid < NN) {
        int r = g_rowptr[gid] + g_boff[blockIdx.x];
        g_rowptr[gid] = r;
        g_fillpos[gid] = r;
    }
    if (blockIdx.x == 0 && tid == 0) g_rowptr[NN] = ETOT;
}

__global__ void fill_kernel(const int* __restrict__ ei) {
    int e = blockIdx.x * blockDim.x + threadIdx.x;
    if (e >= ETOT) return;
    int s, d;
    edge_sd(ei, e, g_stride2, s, d);
    int pos = atomicAdd(&g_fillpos[d], 1);
    g_esrc[pos] = s;
    g_eid[pos] = e;
}

// ---------------- fused softmax + gather: one warp per dst node --------------
__global__ void __launch_bounds__(256) gather_kernel(float* __restrict__ out,
                                                     const float* __restrict__ bias,
                                                     int writeAll) {
    int gw = (blockIdx.x * blockDim.x + threadIdx.x) >> 5;
    int lane = threadIdx.x & 31;
    if (gw >= NN) return;
    const int d = gw;
    const int start = g_rowptr[d];
    const int end   = g_rowptr[d + 1];
    const int h = lane >> 2;

    float adh = g_adst[(size_t)d * 8 + h];

    float m = -3.402823466e38f, ssum = 0.f;
    for (int i = start; i < end; i++) {
        int s = g_esrc[i];
        float lg = lrelu(g_asrc[(size_t)s * 8 + h] + adh);
        float nm = fmaxf(m, lg);
        ssum = ssum * __expf(m - nm) + __expf(lg - nm);
        m = nm;
    }
    float inv = 1.f / (ssum + 1e-16f);

    float4 acc = make_float4(0.f, 0.f, 0.f, 0.f);
    for (int i = start; i < end; i++) {
        int s = g_esrc[i];
        float lg = lrelu(g_asrc[(size_t)s * 8 + h] + adh);
        float al = __expf(lg - m) * inv;
        if (writeAll && (lane & 3) == 0) {
            int eid = g_eid[i];
            out[(size_t)OUT_ELEMS + EI_ELEMS + (size_t)eid * 8 + h] = al;
        }
        float4 hv = *(const float4*)(g_h + (size_t)s * DD + lane * 4);
        acc.x += al * hv.x;
        acc.y += al * hv.y;
        acc.z += al * hv.z;
        acc.w += al * hv.w;
    }

    float4 bv = *(const float4*)(bias + lane * 4);
    acc.x += bv.x; acc.y += bv.y; acc.z += bv.z; acc.w += bv.w;
    *(float4*)(out + (size_t)d * DD + lane * 4) = acc;
}

// ---------------- launch ------------------------------------------------------
extern "C" void kernel_launch(void* const* d_in, const int* in_sizes, int n_in,
                              void* d_out, int out_size) {
    const float* x       = (const float*)d_in[0];
    const int*   ei      = (const int*)d_in[1];
    const float* W       = (const float*)d_in[2];
    const float* att_src = (const float*)d_in[3];
    const float* att_dst = (const float*)d_in[4];
    const float* bias    = (const float*)d_in[5];
    float* out = (float*)d_out;

    int writeAll = (out_size >= OUT_ELEMS + EI_ELEMS + ALPHA_ELEMS) ? 1 : 0;

    static int smem_set = 0;
    if (!smem_set) {
        cudaFuncSetAttribute(gemm_kernel,
                             cudaFuncAttributeMaxDynamicSharedMemorySize, GEMM_SMEM);
        smem_set = 1;
    }

    detect_kernel<<<1, 1>>>(ei);
    init_kernel<<<256, 256>>>(out, ei, writeAll, 0);
    init_kernel<<<512, 256>>>(out, ei, writeAll, 1);
    prep_wa_kernel<<<1, 128>>>(W, att_src, att_dst);
    gemm_kernel<<<dim3((NN + GR - 1) / GR, DD / GCOL), 256, GEMM_SMEM>>>(x, W);
    attn2_kernel<<<(NN + 31) / 32, 128>>>(x);
    scan1_kernel<<<NB1, SB>>>();
    scan2_kernel<<<1, 256>>>();
    scan3_kernel<<<NB1, SB>>>();
    fill_kernel<<<(ETOT + 255) / 256, 256>>>(ei);
    gather_kernel<<<(NN * 32 + 255) / 256, 256>>>(out, bias, writeAll);
}

// round 9
// speedup vs baseline: 1.0558x; 1.0558x over previous
#include <cuda_runtime.h>
#include <math.h>

// Problem constants
#define NN 100000
#define DD 128
#define HH 8
#define CC 16
#define EE 800000
#define ETOT (EE + NN)              // 900000
#define OUT_ELEMS (NN * DD)         // 12,800,000
#define EI_ELEMS  (2 * ETOT)        //  1,800,000
#define ALPHA_ELEMS (ETOT * HH)     //  7,200,000
#define NEG_SLOPE 0.2f

#define SB 512
#define NB1 ((NN + SB - 1) / SB)    // 196 scan blocks

// GEMM tiling: block = 128 rows x 64 cols, 256 threads, thread = 4 rows x 8 cols
#define GR 128
#define GCOL 64
#define XS 132                       // x tile row stride (floats), row-major
#define WS 68                        // W tile row stride (floats)
#define GEMM_SMEM ((GR * XS + DD * WS + 2 * GCOL) * 4)

// ---------------- device scratch (static; 16B-aligned) -----------------------
__device__ __align__(16) float g_h[(size_t)NN * DD];      // 51.2 MB
__device__ __align__(16) float g_asrc[(size_t)NN * HH];   // 3.2 MB
__device__ __align__(16) float g_adst[(size_t)NN * HH];   // 3.2 MB
__device__ int g_cnt[NN];
__device__ int g_rowptr[NN + 1];
__device__ int g_fillpos[NN];
__device__ int g_bsum[256];
__device__ int g_boff[256];
__device__ int g_esrc[ETOT];
__device__ int g_eid[ETOT];
__device__ int g_stride2;   // 1 if edge buffer is int64-backed (low words, stride 2)

// ---------------- helpers ----------------------------------------------------
__device__ __forceinline__ void ffma2(unsigned long long& acc,
                                      unsigned long long x2,
                                      unsigned long long w2) {
    asm("fma.rn.f32x2 %0, %1, %2, %0;" : "+l"(acc) : "l"(x2), "l"(w2));
}
__device__ __forceinline__ float lrelu(float v) {
    return v > 0.f ? v : NEG_SLOPE * v;
}
__device__ __forceinline__ void edge_sd(const int* __restrict__ ei, int e, int st2,
                                        int& s, int& d) {
    if (e < EE) {
        if (st2) { s = ei[2 * e]; d = ei[2 * (EE + e)]; }
        else     { s = ei[e];     d = ei[EE + e]; }
    } else {
        s = d = e - EE;
    }
}

// ---------------- init phase 0: zero histogram + detect edge dtype -----------
__global__ void init0_kernel(const int* __restrict__ ei) {
    int i = blockIdx.x * blockDim.x + threadIdx.x;
    int stride = gridDim.x * blockDim.x;
    for (int t = i; t < NN; t += stride) g_cnt[t] = 0;
    if (blockIdx.x == 0 && threadIdx.x == 0) {
        int nz = 0;
        #pragma unroll
        for (int q = 0; q < 64; q++) nz |= ei[2 * q + 1];
        g_stride2 = (nz == 0) ? 1 : 0;
    }
}

// ---------------- init phase 1: histogram + optional ei copy -----------------
__global__ void init1_kernel(float* __restrict__ out, const int* __restrict__ ei,
                             int writeAll) {
    const int st2 = g_stride2;
    int i = blockIdx.x * blockDim.x + threadIdx.x;
    int stride = gridDim.x * blockDim.x;
    for (int t = i; t < ETOT; t += stride) {
        int s, d;
        edge_sd(ei, t, st2, s, d);
        atomicAdd(&g_cnt[d], 1);
        if (writeAll) {
            out[(size_t)OUT_ELEMS + t]        = (float)s;
            out[(size_t)OUT_ELEMS + ETOT + t] = (float)d;
        }
    }
}

// ---------------- GEMM: h = x @ W, 128x64 blocks, col-pair packed accs -------
// Fused: a_src/a_dst per (row, head) computed in epilogue (block covers whole heads).
__global__ void __launch_bounds__(256) gemm_kernel(const float* __restrict__ x,
                                                   const float* __restrict__ W,
                                                   const float* __restrict__ att_s,
                                                   const float* __restrict__ att_d) {
    extern __shared__ __align__(16) float sm[];
    float* xs = sm;                        // [128 r][XS]  row-major
    float* ws = sm + GR * XS;              // [128 k][WS]
    float* as_s = ws + DD * WS;            // [64] att_src slice for this block
    float* ad_s = as_s + GCOL;             // [64]

    const int tid  = threadIdx.x;
    const int row0 = blockIdx.x * GR;
    const int col0 = blockIdx.y * GCOL;

    // Stage x row-major (coalesced gmem, conflict-free smem stores)
    #pragma unroll
    for (int it = 0; it < 16; it++) {
        int i = tid + 256 * it;            // 0..4095
        int r = i >> 5, k4 = (i & 31) * 4;
        int row = row0 + r;
        float4 v = (row < NN) ? *(const float4*)(x + (size_t)row * DD + k4)
                              : make_float4(0.f, 0.f, 0.f, 0.f);
        *(float4*)(xs + r * XS + k4) = v;
    }
    // Stage W tile
    #pragma unroll
    for (int it = 0; it < 8; it++) {
        int i = tid + 256 * it;            // 0..2047
        int k = i >> 4, c4 = (i & 15) * 4;
        *(float4*)(ws + k * WS + c4) = *(const float4*)(W + (size_t)k * DD + col0 + c4);
    }
    if (tid < GCOL) {
        as_s[tid] = att_s[col0 + tid];
        ad_s[tid] = att_d[col0 + tid];
    }
    __syncthreads();

    const int cg = tid & 7;               // col group: cols cg*8..cg*8+7
    const int rg = tid >> 3;              // row group: rows rg*4..rg*4+3
    const float* xrow = xs + rg * 4 * XS;
    const float* wrow = ws + cg * 8;

    unsigned long long acc[4][4];         // [row][col-pair]
    #pragma unroll
    for (int i = 0; i < 4; i++)
        #pragma unroll
        for (int c = 0; c < 4; c++) acc[i][c] = 0ull;

    #pragma unroll 4
    for (int k = 0; k < DD; k++) {
        unsigned long long x2[4];
        #pragma unroll
        for (int i = 0; i < 4; i++) {
            float xv = xrow[i * XS + k];
            asm("mov.b64 %0, {%1,%1};" : "=l"(x2[i]) : "f"(xv));
        }
        ulonglong2 wa = *(const ulonglong2*)(wrow + k * WS);
        ulonglong2 wb = *(const ulonglong2*)(wrow + k * WS + 4);
        #pragma unroll
        for (int i = 0; i < 4; i++) {
            ffma2(acc[i][0], x2[i], wa.x);
            ffma2(acc[i][1], x2[i], wa.y);
            ffma2(acc[i][2], x2[i], wb.x);
            ffma2(acc[i][3], x2[i], wb.y);
        }
    }

    // att slices for my 8 cols
    float av[8], bv[8];
    #pragma unroll
    for (int j = 0; j < 8; j++) { av[j] = as_s[cg * 8 + j]; bv[j] = ad_s[cg * 8 + j]; }
    const int head = (col0 + cg * 8) >> 4;

    #pragma unroll
    for (int i = 0; i < 4; i++) {
        float v[8];
        #pragma unroll
        for (int c = 0; c < 4; c++)
            asm("mov.b64 {%0,%1}, %2;" : "=f"(v[2 * c]), "=f"(v[2 * c + 1]) : "l"(acc[i][c]));
        int row = row0 + rg * 4 + i;
        if (row < NN) {
            *(float4*)(g_h + (size_t)row * DD + col0 + cg * 8) =
                make_float4(v[0], v[1], v[2], v[3]);
            *(float4*)(g_h + (size_t)row * DD + col0 + cg * 8 + 4) =
                make_float4(v[4], v[5], v[6], v[7]);
        }
        // fused attention dots: partial over my 8 cols, pair-reduce with cg^1
        float ss = 0.f, sd = 0.f;
        #pragma unroll
        for (int j = 0; j < 8; j++) { ss += v[j] * av[j]; sd += v[j] * bv[j]; }
        ss += __shfl_xor_sync(0xffffffffu, ss, 1);
        sd += __shfl_xor_sync(0xffffffffu, sd, 1);
        if ((cg & 1) == 0 && row < NN) {
            g_asrc[(size_t)row * 8 + head] = ss;
            g_adst[(size_t)row * 8 + head] = sd;
        }
    }
}

// ---------------- CSR build --------------------------------------------------
__global__ void scan1_kernel() {
    __shared__ int sm[SB];
    int tid = threadIdx.x;
    int gid = blockIdx.x * SB + tid;
    int v = (gid < NN) ? g_cnt[gid] : 0;
    sm[tid] = v;
    __syncthreads();
    for (int off = 1; off < SB; off <<= 1) {
        int t = (tid >= off) ? sm[tid - off] : 0;
        __syncthreads();
        sm[tid] += t;
        __syncthreads();
    }
    if (gid < NN) g_rowptr[gid] = sm[tid] - v;
    if (tid == SB - 1) g_bsum[blockIdx.x] = sm[tid];
}

__global__ void scan2_kernel() {
    __shared__ int sm[256];
    int tid = threadIdx.x;
    int v = (tid < NB1) ? g_bsum[tid] : 0;
    sm[tid] = v;
    __syncthreads();
    for (int off = 1; off < 256; off <<= 1) {
        int t = (tid >= off) ? sm[tid - off] : 0;
        __syncthreads();
        sm[tid] += t;
        __syncthreads();
    }
    g_boff[tid] = sm[tid] - v;
}

__global__ void scan3_kernel() {
    int tid = threadIdx.x;
    int gid = blockIdx.x * SB + tid;
    if (gid < NN) {
        int r = g_rowptr[gid] + g_boff[blockIdx.x];
        g_rowptr[gid] = r;
        g_fillpos[gid] = r;
    }
    if (blockIdx.x == 0 && tid == 0) g_rowptr[NN] = ETOT;
}

__global__ void fill_kernel(const int* __restrict__ ei) {
    int e = blockIdx.x * blockDim.x + threadIdx.x;
    if (e >= ETOT) return;
    int s, d;
    edge_sd(ei, e, g_stride2, s, d);
    int pos = atomicAdd(&g_fillpos[d], 1);
    g_esrc[pos] = s;
    g_eid[pos] = e;
}

// ---------------- fused softmax + gather: one warp per dst node --------------
__global__ void __launch_bounds__(256) gather_kernel(float* __restrict__ out,
                                                     const float* __restrict__ bias,
                                                     int writeAll) {
    int gw = (blockIdx.x * blockDim.x + threadIdx.x) >> 5;
    int lane = threadIdx.x & 31;
    if (gw >= NN) return;
    const int d = gw;
    const int start = g_rowptr[d];
    const int end   = g_rowptr[d + 1];
    const int h = lane >> 2;

    float adh = g_adst[(size_t)d * 8 + h];

    float m = -3.402823466e38f, ssum = 0.f;
    for (int i = start; i < end; i++) {
        int s = g_esrc[i];
        float lg = lrelu(g_asrc[(size_t)s * 8 + h] + adh);
        float nm = fmaxf(m, lg);
        ssum = ssum * __expf(m - nm) + __expf(lg - nm);
        m = nm;
    }
    float inv = 1.f / (ssum + 1e-16f);

    float4 acc = make_float4(0.f, 0.f, 0.f, 0.f);
    for (int i = start; i < end; i++) {
        int s = g_esrc[i];
        float lg = lrelu(g_asrc[(size_t)s * 8 + h] + adh);
        float al = __expf(lg - m) * inv;
        if (writeAll && (lane & 3) == 0) {
            int eid = g_eid[i];
            out[(size_t)OUT_ELEMS + EI_ELEMS + (size_t)eid * 8 + h] = al;
        }
        float4 hv = *(const float4*)(g_h + (size_t)s * DD + lane * 4);
        acc.x += al * hv.x;
        acc.y += al * hv.y;
        acc.z += al * hv.z;
        acc.w += al * hv.w;
    }

    float4 bv = *(const float4*)(bias + lane * 4);
    acc.x += bv.x; acc.y += bv.y; acc.z += bv.z; acc.w += bv.w;
    *(float4*)(out + (size_t)d * DD + lane * 4) = acc;
}

// ---------------- launch ------------------------------------------------------
extern "C" void kernel_launch(void* const* d_in, const int* in_sizes, int n_in,
                              void* d_out, int out_size) {
    const float* x       = (const float*)d_in[0];
    const int*   ei      = (const int*)d_in[1];
    const float* W       = (const float*)d_in[2];
    const float* att_src = (const float*)d_in[3];
    const float* att_dst = (const float*)d_in[4];
    const float* bias    = (const float*)d_in[5];
    float* out = (float*)d_out;

    int writeAll = (out_size >= OUT_ELEMS + EI_ELEMS + ALPHA_ELEMS) ? 1 : 0;

    static int smem_set = 0;
    if (!smem_set) {
        cudaFuncSetAttribute(gemm_kernel,
                             cudaFuncAttributeMaxDynamicSharedMemorySize, GEMM_SMEM);
        smem_set = 1;
    }

    init0_kernel<<<256, 256>>>(ei);
    init1_kernel<<<512, 256>>>(out, ei, writeAll);
    gemm_kernel<<<dim3((NN + GR - 1) / GR, DD / GCOL), 256, GEMM_SMEM>>>(x, W, att_src, att_dst);
    scan1_kernel<<<NB1, SB>>>();
    scan2_kernel<<<1, 256>>>();
    scan3_kernel<<<NB1, SB>>>();
    fill_kernel<<<(ETOT + 255) / 256, 256>>>(ei);
    gather_kernel<<<(NN * 32 + 255) / 256, 256>>>(out, bias, writeAll);
}

// round 10
// speedup vs baseline: 1.2431x; 1.1774x over previous
#include <cuda_runtime.h>
#include <math.h>

// Problem constants
#define NN 100000
#define DD 128
#define HH 8
#define CC 16
#define EE 800000
#define ETOT (EE + NN)              // 900000
#define OUT_ELEMS (NN * DD)         // 12,800,000
#define EI_ELEMS  (2 * ETOT)        //  1,800,000
#define ALPHA_ELEMS (ETOT * HH)     //  7,200,000
#define NEG_SLOPE 0.2f

#define SB 512
#define NB1 ((NN + SB - 1) / SB)    // 196 scan blocks

// GEMM tiling: block = 128 rows x 128 cols (full width), 256 threads,
// thread tile = 8 rows (cyclic, stride 16) x 8 cols.
#define GR 128
#define XS 132                       // x tile row stride (floats)
#define WS 132                       // W tile row stride (floats)
#define GEMM_SMEM ((GR * XS + DD * WS) * 4)   // 135168 B

// ---------------- device scratch (static; 16B-aligned) -----------------------
__device__ __align__(16) float g_h[(size_t)NN * DD];      // 51.2 MB
__device__ __align__(16) float g_asrc[(size_t)NN * HH];   // 3.2 MB
__device__ __align__(16) float g_adst[(size_t)NN * HH];   // 3.2 MB
__device__ int g_cnt[NN];
__device__ int g_rowptr[NN + 1];
__device__ int g_fillpos[NN];
__device__ int g_bsum[256];
__device__ int g_boff[256];
__device__ int g_esrc[ETOT];
__device__ int g_eid[ETOT];
__device__ int g_stride2;   // 1 if edge buffer is int64-backed (low words, stride 2)

// ---------------- helpers ----------------------------------------------------
__device__ __forceinline__ void ffma2(unsigned long long& acc,
                                      unsigned long long x2,
                                      unsigned long long w2) {
    asm("fma.rn.f32x2 %0, %1, %2, %0;" : "+l"(acc) : "l"(x2), "l"(w2));
}
__device__ __forceinline__ float lrelu(float v) {
    return v > 0.f ? v : NEG_SLOPE * v;
}
__device__ __forceinline__ void edge_sd(const int* __restrict__ ei, int e, int st2,
                                        int& s, int& d) {
    if (e < EE) {
        if (st2) { s = ei[2 * e]; d = ei[2 * (EE + e)]; }
        else     { s = ei[e];     d = ei[EE + e]; }
    } else {
        s = d = e - EE;
    }
}

// ---------------- init phase 0: zero histogram + detect edge dtype -----------
__global__ void init0_kernel(const int* __restrict__ ei) {
    int i = blockIdx.x * blockDim.x + threadIdx.x;
    int stride = gridDim.x * blockDim.x;
    for (int t = i; t < NN; t += stride) g_cnt[t] = 0;
    if (blockIdx.x == 0 && threadIdx.x == 0) {
        int nz = 0;
        #pragma unroll
        for (int q = 0; q < 64; q++) nz |= ei[2 * q + 1];
        g_stride2 = (nz == 0) ? 1 : 0;
    }
}

// ---------------- init phase 1: histogram + optional ei copy -----------------
__global__ void init1_kernel(float* __restrict__ out, const int* __restrict__ ei,
                             int writeAll) {
    const int st2 = g_stride2;
    int i = blockIdx.x * blockDim.x + threadIdx.x;
    int stride = gridDim.x * blockDim.x;
    for (int t = i; t < ETOT; t += stride) {
        int s, d;
        edge_sd(ei, t, st2, s, d);
        atomicAdd(&g_cnt[d], 1);
        if (writeAll) {
            out[(size_t)OUT_ELEMS + t]        = (float)s;
            out[(size_t)OUT_ELEMS + ETOT + t] = (float)d;
        }
    }
}

// ---------------- GEMM: h = x @ W, 128x128 block, 8x8 thread tile ------------
// cg = tid & 15 -> cols cg*8..cg*8+7 ; rg = tid >> 4 -> rows rg, rg+16, ..., rg+112.
// Fused attention dots in epilogue (8 cols always within one head).
__global__ void __launch_bounds__(256) gemm_kernel(const float* __restrict__ x,
                                                   const float* __restrict__ W,
                                                   const float* __restrict__ att_s,
                                                   const float* __restrict__ att_d) {
    extern __shared__ __align__(16) float sm[];
    float* xs = sm;                        // [128 r][XS]  row-major
    float* ws = sm + GR * XS;              // [128 k][WS]

    const int tid  = threadIdx.x;
    const int row0 = blockIdx.x * GR;

    // Stage x row-major (coalesced gmem, conflict-free smem stores)
    #pragma unroll
    for (int it = 0; it < 16; it++) {
        int i = tid + 256 * it;            // 0..4095
        int r = i >> 5, k4 = (i & 31) * 4;
        int row = row0 + r;
        float4 v = (row < NN) ? *(const float4*)(x + (size_t)row * DD + k4)
                              : make_float4(0.f, 0.f, 0.f, 0.f);
        *(float4*)(xs + r * XS + k4) = v;
    }
    // Stage full W (128x128)
    #pragma unroll
    for (int it = 0; it < 16; it++) {
        int i = tid + 256 * it;            // 0..4095
        int k = i >> 5, c4 = (i & 31) * 4;
        *(float4*)(ws + k * WS + c4) = *(const float4*)(W + (size_t)k * DD + c4);
    }
    __syncthreads();

    const int cg = tid & 15;              // col group: cols cg*8..cg*8+7
    const int rg = tid >> 4;              // row group: rows rg + i*16
    const float* wrow = ws + cg * 8;

    unsigned long long acc[8][4];         // [row][col-pair]
    #pragma unroll
    for (int i = 0; i < 8; i++)
        #pragma unroll
        for (int c = 0; c < 4; c++) acc[i][c] = 0ull;

    #pragma unroll 2
    for (int k = 0; k < DD; k++) {
        ulonglong2 wa = *(const ulonglong2*)(wrow + k * WS);
        ulonglong2 wb = *(const ulonglong2*)(wrow + k * WS + 4);
        unsigned long long x2[8];
        #pragma unroll
        for (int i = 0; i < 8; i++) {
            float xv = xs[(rg + i * 16) * XS + k];
            asm("mov.b64 %0, {%1,%1};" : "=l"(x2[i]) : "f"(xv));
        }
        #pragma unroll
        for (int i = 0; i < 8; i++) {
            ffma2(acc[i][0], x2[i], wa.x);
            ffma2(acc[i][1], x2[i], wa.y);
            ffma2(acc[i][2], x2[i], wb.x);
            ffma2(acc[i][3], x2[i], wb.y);
        }
    }

    // att slices for my 8 cols (L2/const-cached loads, tiny)
    float av[8], bv[8];
    #pragma unroll
    for (int j = 0; j < 8; j++) { av[j] = att_s[cg * 8 + j]; bv[j] = att_d[cg * 8 + j]; }
    const int head = cg >> 1;

    #pragma unroll
    for (int i = 0; i < 8; i++) {
        float v[8];
        #pragma unroll
        for (int c = 0; c < 4; c++)
            asm("mov.b64 {%0,%1}, %2;" : "=f"(v[2 * c]), "=f"(v[2 * c + 1]) : "l"(acc[i][c]));
        int row = row0 + rg + i * 16;
        if (row < NN) {
            *(float4*)(g_h + (size_t)row * DD + cg * 8) =
                make_float4(v[0], v[1], v[2], v[3]);
            *(float4*)(g_h + (size_t)row * DD + cg * 8 + 4) =
                make_float4(v[4], v[5], v[6], v[7]);
        }
        float ss = 0.f, sd = 0.f;
        #pragma unroll
        for (int j = 0; j < 8; j++) { ss += v[j] * av[j]; sd += v[j] * bv[j]; }
        ss += __shfl_xor_sync(0xffffffffu, ss, 1);
        sd += __shfl_xor_sync(0xffffffffu, sd, 1);
        if ((cg & 1) == 0 && row < NN) {
            g_asrc[(size_t)row * 8 + head] = ss;
            g_adst[(size_t)row * 8 + head] = sd;
        }
    }
}

// ---------------- CSR build --------------------------------------------------
__global__ void scan1_kernel() {
    __shared__ int sm[SB];
    int tid = threadIdx.x;
    int gid = blockIdx.x * SB + tid;
    int v = (gid < NN) ? g_cnt[gid] : 0;
    sm[tid] = v;
    __syncthreads();
    for (int off = 1; off < SB; off <<= 1) {
        int t = (tid >= off) ? sm[tid - off] : 0;
        __syncthreads();
        sm[tid] += t;
        __syncthreads();
    }
    if (gid < NN) g_rowptr[gid] = sm[tid] - v;
    if (tid == SB - 1) g_bsum[blockIdx.x] = sm[tid];
}

__global__ void scan2_kernel() {
    __shared__ int sm[256];
    int tid = threadIdx.x;
    int v = (tid < NB1) ? g_bsum[tid] : 0;
    sm[tid] = v;
    __syncthreads();
    for (int off = 1; off < 256; off <<= 1) {
        int t = (tid >= off) ? sm[tid - off] : 0;
        __syncthreads();
        sm[tid] += t;
        __syncthreads();
    }
    g_boff[tid] = sm[tid] - v;
}

__global__ void scan3_kernel() {
    int tid = threadIdx.x;
    int gid = blockIdx.x * SB + tid;
    if (gid < NN) {
        int r = g_rowptr[gid] + g_boff[blockIdx.x];
        g_rowptr[gid] = r;
        g_fillpos[gid] = r;
    }
    if (blockIdx.x == 0 && tid == 0) g_rowptr[NN] = ETOT;
}

__global__ void fill_kernel(const int* __restrict__ ei) {
    int e = blockIdx.x * blockDim.x + threadIdx.x;
    if (e >= ETOT) return;
    int s, d;
    edge_sd(ei, e, g_stride2, s, d);
    int pos = atomicAdd(&g_fillpos[d], 1);
    g_esrc[pos] = s;
    g_eid[pos] = e;
}

// ---------------- fused softmax + gather: one warp per dst node --------------
__global__ void __launch_bounds__(256) gather_kernel(float* __restrict__ out,
                                                     const float* __restrict__ bias,
                                                     int writeAll) {
    int gw = (blockIdx.x * blockDim.x + threadIdx.x) >> 5;
    int lane = threadIdx.x & 31;
    if (gw >= NN) return;
    const int d = gw;
    const int start = g_rowptr[d];
    const int end   = g_rowptr[d + 1];
    const int h = lane >> 2;

    float adh = g_adst[(size_t)d * 8 + h];

    float m = -3.402823466e38f, ssum = 0.f;
    for (int i = start; i < end; i++) {
        int s = g_esrc[i];
        float lg = lrelu(g_asrc[(size_t)s * 8 + h] + adh);
        float nm = fmaxf(m, lg);
        ssum = ssum * __expf(m - nm) + __expf(lg - nm);
        m = nm;
    }
    float inv = 1.f / (ssum + 1e-16f);

    float4 acc = make_float4(0.f, 0.f, 0.f, 0.f);
    for (int i = start; i < end; i++) {
        int s = g_esrc[i];
        float lg = lrelu(g_asrc[(size_t)s * 8 + h] + adh);
        float al = __expf(lg - m) * inv;
        if (writeAll && (lane & 3) == 0) {
            int eid = g_eid[i];
            out[(size_t)OUT_ELEMS + EI_ELEMS + (size_t)eid * 8 + h] = al;
        }
        float4 hv = *(const float4*)(g_h + (size_t)s * DD + lane * 4);
        acc.x += al * hv.x;
        acc.y += al * hv.y;
        acc.z += al * hv.z;
        acc.w += al * hv.w;
    }

    float4 bv = *(const float4*)(bias + lane * 4);
    acc.x += bv.x; acc.y += bv.y; acc.z += bv.z; acc.w += bv.w;
    *(float4*)(out + (size_t)d * DD + lane * 4) = acc;
}

// ---------------- launch ------------------------------------------------------
extern "C" void kernel_launch(void* const* d_in, const int* in_sizes, int n_in,
                              void* d_out, int out_size) {
    const float* x       = (const float*)d_in[0];
    const int*   ei      = (const int*)d_in[1];
    const float* W       = (const float*)d_in[2];
    const float* att_src = (const float*)d_in[3];
    const float* att_dst = (const float*)d_in[4];
    const float* bias    = (const float*)d_in[5];
    float* out = (float*)d_out;

    int writeAll = (out_size >= OUT_ELEMS + EI_ELEMS + ALPHA_ELEMS) ? 1 : 0;

    static int smem_set = 0;
    if (!smem_set) {
        cudaFuncSetAttribute(gemm_kernel,
                             cudaFuncAttributeMaxDynamicSharedMemorySize, GEMM_SMEM);
        smem_set = 1;
    }

    init0_kernel<<<256, 256>>>(ei);
    init1_kernel<<<512, 256>>>(out, ei, writeAll);
    gemm_kernel<<<(NN + GR - 1) / GR, 256, GEMM_SMEM>>>(x, W, att_src, att_dst);
    scan1_kernel<<<NB1, SB>>>();
    scan2_kernel<<<1, 256>>>();
    scan3_kernel<<<NB1, SB>>>();
    fill_kernel<<<(ETOT + 255) / 256, 256>>>(ei);
    gather_kernel<<<(NN * 32 + 255) / 256, 256>>>(out, bias, writeAll);
}